// round 1
// baseline (speedup 1.0000x reference)
#include <cuda_runtime.h>

#define DINL __device__ __forceinline__

constexpr int BATCH = 8192;

// Layer shapes (stride 2, pad 1, k=5):
// L1: 6x32x48  -> 12x15x23
// L2: 12x15x23 -> 24x7x11
// L3: 24x7x11  -> 48x3x5
// L4: 48x3x5   -> 96x1x2
// Linear: (B,192) x (360,192)^T + bl

__device__ short g_y1[(size_t)BATCH * 12 * 15 * 23];
__device__ short g_y2[(size_t)BATCH * 24 * 7 * 11];
__device__ short g_y3[(size_t)BATCH * 48 * 3 * 5];
__device__ short g_y4[(size_t)BATCH * 96 * 1 * 2];

__device__ unsigned long long g_sum[512];   // per-layer offset l*128
__device__ unsigned long long g_sq[512];
__device__ float2 g_coef[512];              // (a, c): bit = a*y + c > 0

__device__ unsigned g_wp1[12 * 5 * 1];
__device__ unsigned g_wp2[24 * 5 * 2];
__device__ unsigned g_wp3[48 * 5 * 4];
__device__ unsigned g_wp4[96 * 5 * 8];
__device__ unsigned g_wlp[360 * 6];

template <int WIDTH>
DINL unsigned wmask_w(int j) {
    int rem = WIDTH - 32 * j;
    return (rem >= 32) ? 0xFFFFFFFFu : ((1u << rem) - 1u);
}

// ---------------------------------------------------------------------------
// Prep: zero BN accumulators + pack all weight sign bits
// ---------------------------------------------------------------------------
template <int CI, int CO>
DINL void pack_w(const float* __restrict__ w, unsigned* __restrict__ outw,
                 int gtid, int gsz) {
    constexpr int NW = (5 * CI + 31) / 32;
    const int tot = CO * 5 * NW;
    for (int u = gtid; u < tot; u += gsz) {
        int co = u / (5 * NW);
        int kh = (u / NW) % 5;
        int j = u % NW;
        unsigned wd = 0;
        for (int b = 0; b < 32; b++) {
            int t = 32 * j + b;
            if (t < 5 * CI) {
                int kw = t / CI, ci = t % CI;
                if (w[((co * CI + ci) * 5 + kh) * 5 + kw] > 0.0f) wd |= 1u << b;
            }
        }
        outw[u] = wd;
    }
}

__global__ void prep_kernel(const float* __restrict__ w1, const float* __restrict__ w2,
                            const float* __restrict__ w3, const float* __restrict__ w4,
                            const float* __restrict__ wl) {
    int gtid = blockIdx.x * blockDim.x + threadIdx.x;
    int gsz = gridDim.x * blockDim.x;
    for (int i = gtid; i < 512; i += gsz) { g_sum[i] = 0ull; g_sq[i] = 0ull; }
    pack_w<6, 12>(w1, g_wp1, gtid, gsz);
    pack_w<12, 24>(w2, g_wp2, gtid, gsz);
    pack_w<24, 48>(w3, g_wp3, gtid, gsz);
    pack_w<48, 96>(w4, g_wp4, gtid, gsz);
    for (int u = gtid; u < 360 * 6; u += gsz) {
        int o = u / 6, j = u % 6;
        unsigned wd = 0;
        for (int b = 0; b < 32; b++)
            if (wl[o * 192 + 32 * j + b] > 0.0f) wd |= 1u << b;
        g_wlp[u] = wd;
    }
}

// ---------------------------------------------------------------------------
// BN coefficient kernel: a = g/sqrt(v+eps), c = be - m*a
// ---------------------------------------------------------------------------
__global__ void coeff_kernel(int layer, int CO, double invN,
                             const float* __restrict__ g, const float* __restrict__ be) {
    int c = threadIdx.x;
    if (c < CO) {
        long long S = (long long)g_sum[layer * 128 + c];
        long long Q = (long long)g_sq[layer * 128 + c];
        double m = (double)S * invN;
        double v = (double)Q * invN - m * m;
        double a = (double)g[c] / sqrt(v + 1e-5);
        float af = (float)a;
        float cf = (float)((double)be[c] - m * a);
        g_coef[layer * 128 + c] = make_float2(af, cf);
    }
}

// ---------------------------------------------------------------------------
// Binarized conv layer (popcount). LAYER==1: input is sign(x) in {-1,0,+1}
// (0 only at padding); other layers: input bits in {0,1}.
// Packing: per input row ih, bit index = (iw+1)*CI + ci (left/right pad cols
// included as zeros). Window for (oh,ow,kh): 5*CI bits starting at 2*ow*CI.
// ---------------------------------------------------------------------------
template <int LAYER, int CI, int HI, int WI, int CO, int HO, int WO, int IMGS, int COSPLIT>
__global__ void __launch_bounds__(256) conv_bin(const float* __restrict__ xin) {
    constexpr bool FIRST = (LAYER == 1);
    constexpr int PIXI = HI * WI;
    constexpr int NELEM = CI * PIXI;
    constexpr int PIXO = HO * WO;
    constexpr int ROWBITS = (WI + 2) * CI;
    constexpr int ROWW = (ROWBITS + 31) / 32;
    constexpr int NW = (5 * CI + 31) / 32;
    constexpr int RWA = ROWW + NW + 1;   // guard words (zeroed) for funnel reads
    constexpr int WIDTH = 5 * CI;
    constexpr int COQ = CO / COSPLIT;
    constexpr int NTASK = IMGS * PIXO * COSPLIT;

    __shared__ unsigned char s_bits[IMGS * NELEM];
    __shared__ unsigned s_rows[IMGS * HI * RWA];
    __shared__ unsigned s_wp[CO * 5 * NW];
    __shared__ unsigned s_mrow[FIRST ? RWA : 1];
    __shared__ int s_sum[CO];
    __shared__ int s_sq[CO];
    __shared__ float2 s_coef[FIRST ? 1 : CI];

    const int tid = threadIdx.x;
    const int n0 = blockIdx.x * IMGS;

    // select buffers for this layer (device-side global addresses)
    const short* yin = nullptr;
    short* yout = nullptr;
    const unsigned* wpg = nullptr;
    if constexpr (LAYER == 1) { yout = g_y1; wpg = g_wp1; }
    if constexpr (LAYER == 2) { yin = g_y1; yout = g_y2; wpg = g_wp2; }
    if constexpr (LAYER == 3) { yin = g_y2; yout = g_y3; wpg = g_wp3; }
    if constexpr (LAYER == 4) { yin = g_y3; yout = g_y4; wpg = g_wp4; }
    unsigned long long* gsum = g_sum + (LAYER - 1) * 128;
    unsigned long long* gsq = g_sq + (LAYER - 1) * 128;

    // ---- init ----
    for (int i = tid; i < CO * 5 * NW; i += 256) s_wp[i] = wpg[i];
    for (int i = tid; i < CO; i += 256) { s_sum[i] = 0; s_sq[i] = 0; }
    if constexpr (!FIRST) {
        const float2* cf = g_coef + (LAYER - 2) * 128;
        for (int i = tid; i < CI; i += 256) s_coef[i] = cf[i];
    } else {
        for (int i = tid; i < RWA; i += 256) {
            unsigned w = 0;
            for (int b = 0; b < 32; b++) {
                int t = 32 * i + b;
                int pix = t / CI;
                if (t < ROWBITS && pix >= 1 && pix <= WI) w |= 1u << b;
            }
            s_mrow[i] = w;
        }
    }
    for (int i = tid; i < IMGS * HI * RWA; i += 256) s_rows[i] = 0;
    __syncthreads();

    // ---- stage & binarize ----
    for (int m = 0; m < IMGS; m++) {
        const int n = n0 + m;
        if constexpr (FIRST) {
            const float* xp = xin + (size_t)n * NELEM;
            for (int e = tid; e < NELEM; e += 256)
                s_bits[m * NELEM + e] = (unsigned char)(xp[e] > 0.0f);
        } else {
            const short* yp = yin + (size_t)n * NELEM;
            for (int e = tid; e < NELEM; e += 256) {
                int ci = e / PIXI;
                float2 c = s_coef[ci];
                s_bits[m * NELEM + e] =
                    (unsigned char)(fmaf(c.x, (float)yp[e], c.y) > 0.0f);
            }
        }
    }
    __syncthreads();

    // ---- pack rows ----
    constexpr int TOTW = IMGS * HI * ROWW;
    for (int u = tid; u < TOTW; u += 256) {
        int m = u / (HI * ROWW);
        int rr = u % (HI * ROWW);
        int r = rr / ROWW, j = rr % ROWW;
        unsigned w = 0;
        const unsigned char* bp = &s_bits[m * NELEM + r * WI];
#pragma unroll
        for (int b = 0; b < 32; b++) {
            int t = 32 * j + b;
            int pix = t / CI, ci = t % CI;
            if (pix >= 1 && pix <= WI)
                w |= ((unsigned)bp[ci * PIXI + (pix - 1)]) << b;
        }
        s_rows[(m * HI + r) * RWA + j] = w;
    }
    __syncthreads();

    // ---- conv via popcount ----
    for (int t = tid; t < NTASK; t += 256) {
        int coq = t % COSPLIT;
        int pt = t / COSPLIT;
        int m = pt / PIXO;
        int pix = pt % PIXO;
        int oh = pix / WO, ow = pix % WO;

        unsigned aw[5][NW];
        unsigned mw[FIRST ? 5 : 1][NW];
        int s = 2 * ow * CI;
        int wofs = s >> 5, sh = s & 31;
        int popA = 0;
#pragma unroll
        for (int kh = 0; kh < 5; kh++) {
            int ih = 2 * oh - 1 + kh;
            bool v = (ih >= 0 && ih < HI);
            const unsigned* rw = &s_rows[(m * HI + (v ? ih : 0)) * RWA + wofs];
#pragma unroll
            for (int j = 0; j < NW; j++) {
                unsigned msk = wmask_w<WIDTH>(j);
                unsigned win = __funnelshift_r(rw[j], rw[j + 1], sh) & msk;
                if constexpr (FIRST) {
                    unsigned mwin =
                        __funnelshift_r(s_mrow[wofs + j], s_mrow[wofs + j + 1], sh) & msk;
                    mw[kh][j] = v ? mwin : 0u;
                    aw[kh][j] = win;
                    popA += __popc(mw[kh][j]);
                } else {
                    aw[kh][j] = v ? win : 0u;
                    popA += __popc(aw[kh][j]);
                }
            }
        }
        const int n = n0 + m;
        for (int ic = 0; ic < COQ; ic++) {
            int co = coq * COQ + ic;
            const unsigned* wpc = &s_wp[co * 5 * NW];
            int acc = 0;
#pragma unroll
            for (int kh = 0; kh < 5; kh++)
#pragma unroll
                for (int j = 0; j < NW; j++) {
                    unsigned wv = wpc[kh * NW + j];
                    if constexpr (FIRST)
                        acc += __popc(mw[kh][j] & ~(aw[kh][j] ^ wv));
                    else
                        acc += __popc(aw[kh][j] & wv);
                }
            int dot = 2 * acc - popA;
            yout[((size_t)n * CO + co) * PIXO + pix] = (short)dot;
            atomicAdd(&s_sum[co], dot);
            atomicAdd(&s_sq[co], dot * dot);
        }
    }
    __syncthreads();

    for (int c = tid; c < CO; c += 256) {
        atomicAdd(&gsum[c], (unsigned long long)(long long)s_sum[c]);
        atomicAdd(&gsq[c], (unsigned long long)(long long)s_sq[c]);
    }
}

// ---------------------------------------------------------------------------
// Final binary linear: out[n,o] = 2*popc(bits(n) & wp(o)) - popc(bits(n)) + bl[o]
// ---------------------------------------------------------------------------
__global__ void __launch_bounds__(256) linear_kernel(const float* __restrict__ bl,
                                                     float* __restrict__ out) {
    __shared__ unsigned s_w[360 * 6];
    __shared__ unsigned s_b[32 * 6];
    __shared__ int s_pop[32];
    __shared__ float s_bl[360];
    __shared__ float2 s_coef[96];

    int tid = threadIdx.x;
    for (int i = tid; i < 360 * 6; i += 256) s_w[i] = g_wlp[i];
    for (int i = tid; i < 360; i += 256) s_bl[i] = bl[i];
    for (int i = tid; i < 96; i += 256) s_coef[i] = g_coef[3 * 128 + i];
    __syncthreads();

    int n0 = blockIdx.x * 32;
    for (int u = tid; u < 32 * 6; u += 256) {
        int r = u / 6, j = u % 6;
        const short* yp = g_y4 + (size_t)(n0 + r) * 192 + 32 * j;
        unsigned wd = 0;
#pragma unroll
        for (int b = 0; b < 32; b++) {
            int k = 32 * j + b;
            float2 c = s_coef[k >> 1];
            if (fmaf(c.x, (float)yp[b], c.y) > 0.0f) wd |= 1u << b;
        }
        s_b[u] = wd;
    }
    __syncthreads();
    for (int r = tid; r < 32; r += 256) {
        int p = 0;
#pragma unroll
        for (int j = 0; j < 6; j++) p += __popc(s_b[r * 6 + j]);
        s_pop[r] = p;
    }
    __syncthreads();

    for (int idx = tid; idx < 32 * 360; idx += 256) {
        int r = idx / 360, o = idx % 360;
        int acc = 0;
#pragma unroll
        for (int j = 0; j < 6; j++) acc += __popc(s_b[r * 6 + j] & s_w[o * 6 + j]);
        out[(size_t)(n0 + r) * 360 + o] = (float)(2 * acc - s_pop[r]) + s_bl[o];
    }
}

// ---------------------------------------------------------------------------
// Launch
// ---------------------------------------------------------------------------
extern "C" void kernel_launch(void* const* d_in, const int* in_sizes, int n_in,
                              void* d_out, int out_size) {
    const float* x   = (const float*)d_in[0];
    const float* w1  = (const float*)d_in[1];
    const float* g1  = (const float*)d_in[3];
    const float* be1 = (const float*)d_in[4];
    const float* w2  = (const float*)d_in[5];
    const float* g2  = (const float*)d_in[7];
    const float* be2 = (const float*)d_in[8];
    const float* w3  = (const float*)d_in[9];
    const float* g3  = (const float*)d_in[11];
    const float* be3 = (const float*)d_in[12];
    const float* w4  = (const float*)d_in[13];
    const float* g4  = (const float*)d_in[15];
    const float* be4 = (const float*)d_in[16];
    const float* wl  = (const float*)d_in[17];
    const float* bl  = (const float*)d_in[18];
    float* out = (float*)d_out;

    prep_kernel<<<64, 256>>>(w1, w2, w3, w4, wl);

    conv_bin<1, 6, 32, 48, 12, 15, 23, 1, 1><<<BATCH / 1, 256>>>(x);
    coeff_kernel<<<1, 128>>>(0, 12, 1.0 / ((double)BATCH * 15 * 23), g1, be1);

    conv_bin<2, 12, 15, 23, 24, 7, 11, 4, 1><<<BATCH / 4, 256>>>(nullptr);
    coeff_kernel<<<1, 128>>>(1, 24, 1.0 / ((double)BATCH * 7 * 11), g2, be2);

    conv_bin<3, 24, 7, 11, 48, 3, 5, 16, 1><<<BATCH / 16, 256>>>(nullptr);
    coeff_kernel<<<1, 128>>>(2, 48, 1.0 / ((double)BATCH * 3 * 5), g3, be3);

    conv_bin<4, 48, 3, 5, 96, 1, 2, 16, 8><<<BATCH / 16, 256>>>(nullptr);
    coeff_kernel<<<1, 128>>>(3, 96, 1.0 / ((double)BATCH * 1 * 2), g4, be4);

    linear_kernel<<<BATCH / 32, 256>>>(bl, out);
}

// round 2
// speedup vs baseline: 1.1935x; 1.1935x over previous
#include <cuda_runtime.h>

#define DINL __device__ __forceinline__

constexpr int BATCH = 8192;

// channel-last activations: (n, pix, ci), except y4 which is feature-major (n, 192)
__device__ short g_y1[(size_t)BATCH * 345 * 12];
__device__ short g_y2[(size_t)BATCH * 77 * 24];
__device__ short g_y3[(size_t)BATCH * 15 * 48];
__device__ short g_y4[(size_t)BATCH * 192];

__device__ unsigned long long g_sum[512];   // layer l at offset l*128
__device__ unsigned long long g_sq[512];

__device__ unsigned g_wp1[12 * 5 * 1];
__device__ unsigned g_wp2[24 * 5 * 2];
__device__ unsigned g_wp3[48 * 5 * 4];
__device__ unsigned g_wp4[96 * 5 * 8];
__device__ unsigned g_wlp[360 * 6];

template <int WIDTH>
DINL unsigned wmask_w(int j) {
    int rem = WIDTH - 32 * j;
    return (rem >= 32) ? 0xFFFFFFFFu : ((1u << rem) - 1u);
}

DINL float2 bn_coef(int layer, int c, double invN,
                    const float* __restrict__ g, const float* __restrict__ be) {
    long long S = (long long)g_sum[layer * 128 + c];
    long long Q = (long long)g_sq[layer * 128 + c];
    double m = (double)S * invN;
    double v = (double)Q * invN - m * m;
    double a = (double)g[c] / sqrt(v + 1e-5);
    return make_float2((float)a, (float)((double)be[c] - m * a));
}

// ---------------------------------------------------------------------------
// Prep: zero BN accumulators + pack all weight sign bits
// bit order per (co, kh): t = kw*CI + ci
// ---------------------------------------------------------------------------
template <int CI, int CO>
DINL void pack_w(const float* __restrict__ w, unsigned* __restrict__ outw,
                 int gtid, int gsz) {
    constexpr int NW = (5 * CI + 31) / 32;
    const int tot = CO * 5 * NW;
    for (int u = gtid; u < tot; u += gsz) {
        int co = u / (5 * NW);
        int kh = (u / NW) % 5;
        int j = u % NW;
        unsigned wd = 0;
        for (int b = 0; b < 32; b++) {
            int t = 32 * j + b;
            if (t < 5 * CI) {
                int kw = t / CI, ci = t % CI;
                if (w[((co * CI + ci) * 5 + kh) * 5 + kw] > 0.0f) wd |= 1u << b;
            }
        }
        outw[u] = wd;
    }
}

__global__ void prep_kernel(const float* __restrict__ w1, const float* __restrict__ w2,
                            const float* __restrict__ w3, const float* __restrict__ w4,
                            const float* __restrict__ wl) {
    int gtid = blockIdx.x * blockDim.x + threadIdx.x;
    int gsz = gridDim.x * blockDim.x;
    for (int i = gtid; i < 512; i += gsz) { g_sum[i] = 0ull; g_sq[i] = 0ull; }
    pack_w<6, 12>(w1, g_wp1, gtid, gsz);
    pack_w<12, 24>(w2, g_wp2, gtid, gsz);
    pack_w<24, 48>(w3, g_wp3, gtid, gsz);
    pack_w<48, 96>(w4, g_wp4, gtid, gsz);
    for (int u = gtid; u < 360 * 6; u += gsz) {
        int o = u / 6, j = u % 6;
        unsigned wd = 0;
        for (int b = 0; b < 32; b++)
            if (wl[o * 192 + 32 * j + b] > 0.0f) wd |= 1u << b;
        g_wlp[u] = wd;
    }
}

// ---------------------------------------------------------------------------
// Layer 1: float input, sign in {-1,+1}, padding handled via mask popcount.
// ---------------------------------------------------------------------------
__global__ void __launch_bounds__(256) conv1_kernel(const float* __restrict__ x) {
    constexpr int CI = 6, HI = 32, WI = 48, CO = 12, HO = 15, WO = 23;
    constexpr int PIXI = HI * WI, NELEM = CI * PIXI, PIXO = HO * WO;
    constexpr int ROWBITS = (WI + 2) * CI;       // 300
    constexpr int ROWW = (ROWBITS + 31) / 32;    // 10
    constexpr int RWA = ROWW + 2;                // 12
    constexpr int PITCH = 320;                   // bytes per padded byte-row
    constexpr int IMGS = 4;
    constexpr int NTASK = IMGS * PIXO;           // 1380
    constexpr int ITERS = (NTASK + 255) / 256;   // 6
    constexpr unsigned MASK30 = (1u << 30) - 1u;

    __shared__ unsigned char s_bits[IMGS * HI * PITCH];   // 40960
    __shared__ unsigned s_rows[IMGS * HI * RWA];          // 6144
    __shared__ unsigned s_wp[CO * 5];
    __shared__ unsigned s_mrow[RWA];
    __shared__ int s_sum[CO], s_sq[CO];

    const int tid = threadIdx.x;
    const int n0 = blockIdx.x * IMGS;

    for (int i = tid; i < CO * 5; i += 256) s_wp[i] = g_wp1[i];
    for (int i = tid; i < CO; i += 256) { s_sum[i] = 0; s_sq[i] = 0; }
    for (int i = tid; i < RWA; i += 256) {
        unsigned w = 0;
        for (int b = 0; b < 32; b++) {
            int t = 32 * i + b;
            int p = t / CI;
            if (t < ROWBITS && p >= 1 && p <= WI) w |= 1u << b;
        }
        s_mrow[i] = w;
    }
    for (int i = tid; i < IMGS * HI * RWA; i += 256) s_rows[i] = 0;
    {
        uint4 z = make_uint4(0, 0, 0, 0);
        uint4* p = (uint4*)s_bits;
        for (int i = tid; i < IMGS * HI * PITCH / 16; i += 256) p[i] = z;
    }
    __syncthreads();

    // stage: float4 -> {0,1} bytes, channel-last with 6B pad at row start
    const float4* xp4 = (const float4*)(x + (size_t)n0 * NELEM);
    for (int u = tid; u < IMGS * NELEM / 4; u += 256) {
        float4 v = xp4[u];
        int e = 4 * u;
        int m = e / NELEM, er = e % NELEM;
        int ci = er / PIXI, pr = er % PIXI;
        int ih = pr / WI, iw = pr % WI;
        unsigned char* bp = &s_bits[(m * HI + ih) * PITCH + 6 + iw * CI + ci];
        bp[0]      = (unsigned char)(v.x > 0.0f);
        bp[CI]     = (unsigned char)(v.y > 0.0f);
        bp[2 * CI] = (unsigned char)(v.z > 0.0f);
        bp[3 * CI] = (unsigned char)(v.w > 0.0f);
    }
    __syncthreads();

    // pack: 32 bytes -> 32 bits via nibble multiply trick
    for (int u = tid; u < IMGS * HI * ROWW; u += 256) {
        int row = u / ROWW, j = u % ROWW;
        const uint4* bw = (const uint4*)&s_bits[row * PITCH + 32 * j];
        uint4 a = bw[0], b = bw[1];
        unsigned w = 0;
        w |= ((a.x * 0x01020408u) >> 24);
        w |= ((a.y * 0x01020408u) >> 24) << 4;
        w |= ((a.z * 0x01020408u) >> 24) << 8;
        w |= ((a.w * 0x01020408u) >> 24) << 12;
        w |= ((b.x * 0x01020408u) >> 24) << 16;
        w |= ((b.y * 0x01020408u) >> 24) << 20;
        w |= ((b.z * 0x01020408u) >> 24) << 24;
        w |= ((b.w * 0x01020408u) >> 24) << 28;
        s_rows[row * RWA + j] = w;
    }
    __syncthreads();

    const int lane = tid & 31;
    for (int it = 0; it < ITERS; it++) {
        int t = tid + it * 256;
        bool valid = t < NTASK;
        int tc = valid ? t : NTASK - 1;
        int m = tc / PIXO, pix = tc % PIXO;
        int oh = pix / WO, ow = pix % WO;
        int s = 2 * ow * CI, wofs = s >> 5, sh = s & 31;

        unsigned aw[5], mw[5];
        int popA = 0;
#pragma unroll
        for (int kh = 0; kh < 5; kh++) {
            int ih = 2 * oh - 1 + kh;
            bool v = (ih >= 0 && ih < HI);
            const unsigned* rw = &s_rows[(m * HI + (v ? ih : 0)) * RWA + wofs];
            unsigned win = __funnelshift_r(rw[0], rw[1], sh) & MASK30;
            unsigned mm = __funnelshift_r(s_mrow[wofs], s_mrow[wofs + 1], sh) & MASK30;
            aw[kh] = win;
            mw[kh] = v ? mm : 0u;
            popA += __popc(mw[kh]);
        }
        int dots[CO];
#pragma unroll
        for (int ic = 0; ic < CO; ic++) {
            const unsigned* wpc = &s_wp[ic * 5];
            int acc = 0;
#pragma unroll
            for (int kh = 0; kh < 5; kh++)
                acc += __popc(mw[kh] & ~(aw[kh] ^ wpc[kh]));
            int dot = 2 * acc - popA;
            dots[ic] = dot;
            int d = valid ? dot : 0;
            int s1 = __reduce_add_sync(0xFFFFFFFFu, d);
            int s2 = __reduce_add_sync(0xFFFFFFFFu, d * d);
            if (lane == 0) { atomicAdd(&s_sum[ic], s1); atomicAdd(&s_sq[ic], s2); }
        }
        if (valid) {
            unsigned pk[CO / 2];
#pragma unroll
            for (int i = 0; i < CO / 2; i++)
                pk[i] = (dots[2 * i] & 0xFFFF) | (dots[2 * i + 1] << 16);
            uint2* dst = (uint2*)(g_y1 + ((size_t)(n0 + m) * PIXO + pix) * CO);
            dst[0] = make_uint2(pk[0], pk[1]);
            dst[1] = make_uint2(pk[2], pk[3]);
            dst[2] = make_uint2(pk[4], pk[5]);
        }
    }
    __syncthreads();
    for (int c = tid; c < CO; c += 256) {
        atomicAdd(&g_sum[c], (unsigned long long)(long long)s_sum[c]);
        atomicAdd(&g_sq[c], (unsigned long long)(long long)s_sq[c]);
    }
}

// ---------------------------------------------------------------------------
// Layers 2-4: input bits in {0,1} (sign of clipped BN), channel-last gmem.
// ---------------------------------------------------------------------------
template <int LAYER, int CI, int HI, int WI, int CO, int HO, int WO,
          int IMGS, int COSPLIT, bool COMAJOR>
__global__ void __launch_bounds__(256) conv_rest(const float* __restrict__ gprev,
                                                 const float* __restrict__ beprev,
                                                 double invN) {
    constexpr int PIXI = HI * WI, PIXO = HO * WO;
    constexpr int ROWBITS = (WI + 2) * CI;
    constexpr int ROWW = (ROWBITS + 31) / 32;
    constexpr int NW = (5 * CI + 31) / 32;
    constexpr int RWA = ROWW + NW + 1;
    constexpr int COQ = CO / COSPLIT;
    constexpr int NTASK = IMGS * PIXO * COSPLIT;
    constexpr int ITERS = (NTASK + 255) / 256;
    constexpr int WIDTH = 5 * CI;
    constexpr int CREP = CI + 32;
    constexpr int CHUNK = (COQ > 24) ? 24 : COQ;
    static_assert(COQ % CHUNK == 0, "chunk");

    __shared__ unsigned s_rows[IMGS * HI * RWA];
    __shared__ unsigned s_wp[CO * 5 * NW];
    __shared__ float2 s_crep[CREP];
    __shared__ int s_sum[CO], s_sq[CO];

    const int tid = threadIdx.x;
    const int n0 = blockIdx.x * IMGS;

    const short* yin = nullptr;
    short* yout = nullptr;
    const unsigned* wpg = nullptr;
    if constexpr (LAYER == 2) { yin = g_y1; yout = g_y2; wpg = g_wp2; }
    if constexpr (LAYER == 3) { yin = g_y2; yout = g_y3; wpg = g_wp3; }
    if constexpr (LAYER == 4) { yin = g_y3; yout = g_y4; wpg = g_wp4; }

    for (int i = tid; i < CO * 5 * NW; i += 256) s_wp[i] = wpg[i];
    for (int i = tid; i < CO; i += 256) { s_sum[i] = 0; s_sq[i] = 0; }
    for (int i = tid; i < IMGS * HI * RWA; i += 256) s_rows[i] = 0;
    if (tid < CI) {
        float2 cf = bn_coef(LAYER - 2, tid, invN, gprev, beprev);
        for (int r = tid; r < CREP; r += CI) s_crep[r] = cf;
    }
    __syncthreads();

    // pack: binarize directly from channel-last gmem (contiguous 32 shorts/word)
    for (int u = tid; u < IMGS * HI * ROWW; u += 256) {
        int row = u / ROWW, j = u % ROWW;
        int m = row / HI, r = row % HI;
        const short* yrow = yin + ((size_t)(n0 + m) * PIXI + r * WI) * CI;
        int mo0 = 32 * j - CI;
        int ci0 = (32 * j) % CI;
        unsigned w = 0;
        if (mo0 >= 0 && mo0 + 32 <= WI * CI) {
            const uint2* p = (const uint2*)(yrow + mo0);
            uint2 q[8];
#pragma unroll
            for (int k2 = 0; k2 < 8; k2++) q[k2] = p[k2];
#pragma unroll
            for (int b = 0; b < 32; b++) {
                unsigned raw = (b & 2) ? q[b >> 2].y : q[b >> 2].x;
                short sv = (short)(raw >> ((b & 1) * 16));
                float2 c = s_crep[ci0 + b];
                if (fmaf(c.x, (float)sv, c.y) > 0.0f) w |= 1u << b;
            }
        } else {
#pragma unroll
            for (int b = 0; b < 32; b++) {
                int mo = mo0 + b;
                if (mo >= 0 && mo < WI * CI) {
                    float2 c = s_crep[ci0 + b];
                    short sv = yrow[mo];
                    if (fmaf(c.x, (float)sv, c.y) > 0.0f) w |= 1u << b;
                }
            }
        }
        s_rows[row * RWA + j] = w;
    }
    __syncthreads();

    const int lane = tid & 31;
    for (int it = 0; it < ITERS; it++) {
        int t = tid + it * 256;
        bool valid = t < NTASK;
        int tc = valid ? t : NTASK - 1;
        int coq, pt;
        if constexpr (COSPLIT > 1) {
            coq = tc / (IMGS * PIXO);     // warp-uniform: IMGS*PIXO % 32 == 0
            pt = tc % (IMGS * PIXO);
        } else { coq = 0; pt = tc; }
        int m = pt / PIXO, pix = pt % PIXO;
        int oh = pix / WO, ow = pix % WO;
        int s = 2 * ow * CI, wofs = s >> 5, sh = s & 31;

        unsigned aw[5][NW];
        int popA = 0;
#pragma unroll
        for (int kh = 0; kh < 5; kh++) {
            int ih = 2 * oh - 1 + kh;
            bool v = (ih >= 0 && ih < HI);
            const unsigned* rw = &s_rows[(m * HI + (v ? ih : 0)) * RWA + wofs];
#pragma unroll
            for (int j = 0; j < NW; j++) {
                unsigned msk = wmask_w<WIDTH>(j);
                unsigned win = __funnelshift_r(rw[j], rw[j + 1], sh) & msk;
                aw[kh][j] = v ? win : 0u;
                popA += __popc(aw[kh][j]);
            }
        }
#pragma unroll
        for (int h = 0; h < COQ / CHUNK; h++) {
            int dots[CHUNK];
#pragma unroll
            for (int ic = 0; ic < CHUNK; ic++) {
                int co = coq * COQ + h * CHUNK + ic;
                const unsigned* wpc = &s_wp[co * 5 * NW];
                int acc = 0;
#pragma unroll
                for (int kh = 0; kh < 5; kh++)
#pragma unroll
                    for (int j = 0; j < NW; j++)
                        acc += __popc(aw[kh][j] & wpc[kh * NW + j]);
                int dot = 2 * acc - popA;
                dots[ic] = dot;
                int d = valid ? dot : 0;
                int s1 = __reduce_add_sync(0xFFFFFFFFu, d);
                int s2 = __reduce_add_sync(0xFFFFFFFFu, d * d);
                if (lane == 0) { atomicAdd(&s_sum[co], s1); atomicAdd(&s_sq[co], s2); }
            }
            if (valid) {
                if constexpr (COMAJOR) {
                    short* dst = yout + (size_t)(n0 + m) * (CO * PIXO) + pix;
#pragma unroll
                    for (int ic = 0; ic < CHUNK; ic++)
                        dst[(coq * COQ + h * CHUNK + ic) * PIXO] = (short)dots[ic];
                } else {
                    unsigned pk[CHUNK / 2];
#pragma unroll
                    for (int i2 = 0; i2 < CHUNK / 2; i2++)
                        pk[i2] = (dots[2 * i2] & 0xFFFF) | (dots[2 * i2 + 1] << 16);
                    uint4* dst = (uint4*)(yout + ((size_t)(n0 + m) * PIXO + pix) * CO +
                                          coq * COQ + h * CHUNK);
#pragma unroll
                    for (int i4 = 0; i4 < CHUNK / 8; i4++)
                        dst[i4] = make_uint4(pk[4 * i4], pk[4 * i4 + 1],
                                             pk[4 * i4 + 2], pk[4 * i4 + 3]);
                }
            }
        }
    }
    __syncthreads();
    for (int c = tid; c < CO; c += 256) {
        atomicAdd(&g_sum[(LAYER - 1) * 128 + c],
                  (unsigned long long)(long long)s_sum[c]);
        atomicAdd(&g_sq[(LAYER - 1) * 128 + c],
                  (unsigned long long)(long long)s_sq[c]);
    }
}

// ---------------------------------------------------------------------------
// Final binary linear (inlines layer-4 BN coeff)
// ---------------------------------------------------------------------------
__global__ void __launch_bounds__(256) linear_kernel(const float* __restrict__ g4,
                                                     const float* __restrict__ be4,
                                                     const float* __restrict__ bl,
                                                     float* __restrict__ out) {
    __shared__ unsigned s_w[360 * 6];
    __shared__ unsigned s_b[32 * 6];
    __shared__ int s_pop[32];
    __shared__ float s_bl[360];
    __shared__ float2 s_coef[96];

    int tid = threadIdx.x;
    for (int i = tid; i < 360 * 6; i += 256) s_w[i] = g_wlp[i];
    for (int i = tid; i < 360; i += 256) s_bl[i] = bl[i];
    if (tid < 96) s_coef[tid] = bn_coef(3, tid, 1.0 / ((double)BATCH * 2), g4, be4);
    __syncthreads();

    int n0 = blockIdx.x * 32;
    for (int u = tid; u < 32 * 6; u += 256) {
        int r = u / 6, j = u % 6;
        const uint4* yp = (const uint4*)(g_y4 + (size_t)(n0 + r) * 192 + 32 * j);
        uint4 q0 = yp[0], q1 = yp[1], q2 = yp[2], q3 = yp[3];
        unsigned qq[16] = {q0.x, q0.y, q0.z, q0.w, q1.x, q1.y, q1.z, q1.w,
                           q2.x, q2.y, q2.z, q2.w, q3.x, q3.y, q3.z, q3.w};
        unsigned wd = 0;
#pragma unroll
        for (int b = 0; b < 32; b++) {
            short sv = (short)(qq[b >> 1] >> ((b & 1) * 16));
            int k = 32 * j + b;
            float2 c = s_coef[k >> 1];
            if (fmaf(c.x, (float)sv, c.y) > 0.0f) wd |= 1u << b;
        }
        s_b[u] = wd;
    }
    __syncthreads();
    for (int r = tid; r < 32; r += 256) {
        int p = 0;
#pragma unroll
        for (int j = 0; j < 6; j++) p += __popc(s_b[r * 6 + j]);
        s_pop[r] = p;
    }
    __syncthreads();

    for (int idx = tid; idx < 32 * 360; idx += 256) {
        int r = idx / 360, o = idx % 360;
        int acc = 0;
#pragma unroll
        for (int j = 0; j < 6; j++) acc += __popc(s_b[r * 6 + j] & s_w[o * 6 + j]);
        out[(size_t)(n0 + r) * 360 + o] = (float)(2 * acc - s_pop[r]) + s_bl[o];
    }
}

// ---------------------------------------------------------------------------
// Launch
// ---------------------------------------------------------------------------
extern "C" void kernel_launch(void* const* d_in, const int* in_sizes, int n_in,
                              void* d_out, int out_size) {
    const float* x   = (const float*)d_in[0];
    const float* w1  = (const float*)d_in[1];
    const float* g1  = (const float*)d_in[3];
    const float* be1 = (const float*)d_in[4];
    const float* w2  = (const float*)d_in[5];
    const float* g2  = (const float*)d_in[7];
    const float* be2 = (const float*)d_in[8];
    const float* w3  = (const float*)d_in[9];
    const float* g3  = (const float*)d_in[11];
    const float* be3 = (const float*)d_in[12];
    const float* w4  = (const float*)d_in[13];
    const float* g4  = (const float*)d_in[15];
    const float* be4 = (const float*)d_in[16];
    const float* wl  = (const float*)d_in[17];
    const float* bl  = (const float*)d_in[18];
    float* out = (float*)d_out;

    prep_kernel<<<64, 256>>>(w1, w2, w3, w4, wl);

    conv1_kernel<<<BATCH / 4, 256>>>(x);

    conv_rest<2, 12, 15, 23, 24, 7, 11, 16, 1, false>
        <<<BATCH / 16, 256>>>(g1, be1, 1.0 / ((double)BATCH * 345));

    conv_rest<3, 24, 7, 11, 48, 3, 5, 16, 1, false>
        <<<BATCH / 16, 256>>>(g2, be2, 1.0 / ((double)BATCH * 77));

    conv_rest<4, 48, 3, 5, 96, 1, 2, 16, 8, true>
        <<<BATCH / 16, 256>>>(g3, be3, 1.0 / ((double)BATCH * 15));

    linear_kernel<<<BATCH / 32, 256>>>(g4, be4, bl, out);
}